// round 2
// baseline (speedup 1.0000x reference)
#include <cuda_runtime.h>
#include <math.h>

// Problem constants
#define BB   16
#define CC   256
#define HH   64
#define WW   64
#define KK   7
#define HID  64          // C/4
#define HW   (HH*WW)     // 4096
#define KTAP (KK*KK)     // 49

// Scratch (device globals are the sanctioned workaround for no-alloc rule)
__device__ float g_pooled[BB*CC];          // [B,C]
__device__ float g_h[BB*HID];              // [B,64]
__device__ float g_fused[BB*CC*KTAP];      // [B,C,49]
__device__ float g_dwout[(size_t)BB*CC*HW];// [B,C,H,W]  64 MiB

// ---------------------------------------------------------------------------
// 1) Global average pool: one block per (b,c), 256 threads reduce 4096 elems
// ---------------------------------------------------------------------------
__global__ void pool_kernel(const float* __restrict__ x) {
    int bc = blockIdx.x;                 // b*C + c
    const float4* p = (const float4*)(x + (size_t)bc * HW);
    float s = 0.f;
    #pragma unroll
    for (int i = 0; i < HW/4/256; i++) {
        float4 v = p[threadIdx.x + i*256];
        s += (v.x + v.y) + (v.z + v.w);
    }
    for (int o = 16; o > 0; o >>= 1) s += __shfl_down_sync(0xffffffffu, s, o);
    __shared__ float partial[8];
    if ((threadIdx.x & 31) == 0) partial[threadIdx.x >> 5] = s;
    __syncthreads();
    if (threadIdx.x == 0) {
        float t = 0.f;
        #pragma unroll
        for (int w = 0; w < 8; w++) t += partial[w];
        g_pooled[bc] = t * (1.0f / HW);
    }
}

// ---------------------------------------------------------------------------
// 2a) h = gelu(pooled @ w1.T + b1)   one block per b, 64 threads
// ---------------------------------------------------------------------------
__global__ void mlp1_kernel(const float* __restrict__ w1,
                            const float* __restrict__ b1) {
    int b = blockIdx.x;
    __shared__ float sp[CC];
    for (int i = threadIdx.x; i < CC; i += 64) sp[i] = g_pooled[b*CC + i];
    __syncthreads();
    int j = threadIdx.x;                 // 0..63
    const float* wr = w1 + (size_t)j * CC;
    float acc = b1[j];
    #pragma unroll 8
    for (int c = 0; c < CC; c++) acc += sp[c] * wr[c];
    // exact GELU
    float g = 0.5f * acc * (1.0f + erff(acc * 0.70710678118654752f));
    g_h[b*HID + j] = g;
}

// ---------------------------------------------------------------------------
// 2b) fused[b,c,tap] = dw[c,tap] + (h[b] . w2[c*49+tap]) + b2[c*49+tap]
//     one block per (b,c), 64 threads (49 active)
// ---------------------------------------------------------------------------
__global__ void mlp2_kernel(const float* __restrict__ dw_weight,
                            const float* __restrict__ w2,
                            const float* __restrict__ b2) {
    int bc = blockIdx.x;
    int b = bc / CC, c = bc % CC;
    __shared__ float sh[HID];
    if (threadIdx.x < HID) sh[threadIdx.x] = g_h[b*HID + threadIdx.x];
    __syncthreads();
    int t = threadIdx.x;
    if (t < KTAP) {
        int m = c * KTAP + t;            // row of w2
        const float* wr = w2 + (size_t)m * HID;
        float acc = b2[m];
        #pragma unroll
        for (int j = 0; j < HID; j++) acc += sh[j] * wr[j];
        g_fused[(size_t)bc * KTAP + t] = dw_weight[m] + acc;
    }
}

// ---------------------------------------------------------------------------
// 3) Depthwise 7x7 conv (cross-correlation, pad 3) per (b,c) plane.
//    One block per (b,c): load 70x70 haloed tile into smem, 256 threads
//    compute 16 outputs each. Interior rows loaded with float4.
// ---------------------------------------------------------------------------
#define TS 70
#define TSTRIDE 72
__global__ void dwconv_kernel(const float* __restrict__ x) {
    int bc = blockIdx.x;
    __shared__ float tile[TS * TSTRIDE];
    __shared__ float wgt[KTAP];
    if (threadIdx.x < KTAP) wgt[threadIdx.x] = g_fused[(size_t)bc * KTAP + threadIdx.x];

    const float* xp = x + (size_t)bc * HW;
    // Interior: 64 rows x 64 cols, float4. 64*16 = 1024 vec loads, 4 per thread.
    {
        const float4* xv = (const float4*)xp;
        #pragma unroll
        for (int r = 0; r < 4; r++) {
            int idx = threadIdx.x + r*256;         // 0..1023
            int gy = idx >> 4, gx4 = idx & 15;     // row, vec-col
            float4 v = xv[gy*16 + gx4];
            float* d = &tile[(gy+3)*TSTRIDE + 3 + gx4*4];
            d[0] = v.x; d[1] = v.y; d[2] = v.z; d[3] = v.w;
        }
    }
    // Halo: zero borders (3 rows top/bottom full width, 3 cols left/right)
    for (int i = threadIdx.x; i < TS*3; i += 256) {     // top 3 rows
        int ty = i / TS, tx = i % TS;
        tile[ty*TSTRIDE + tx] = 0.f;
        tile[(ty+67)*TSTRIDE + tx] = 0.f;               // bottom 3 rows
    }
    for (int i = threadIdx.x; i < 64*3; i += 256) {     // side cols (rows 3..66)
        int ty = i / 3 + 3, tx = i % 3;
        tile[ty*TSTRIDE + tx] = 0.f;
        tile[ty*TSTRIDE + 67 + tx] = 0.f;
    }
    __syncthreads();

    float4* op = (float4*)(g_dwout + (size_t)bc * HW);
    #pragma unroll
    for (int i = 0; i < 4; i++) {
        int idx = threadIdx.x + i*256;       // vec index 0..1023
        int y = idx >> 4, x4 = (idx & 15) * 4;
        float a0 = 0.f, a1 = 0.f, a2 = 0.f, a3 = 0.f;
        #pragma unroll
        for (int ky = 0; ky < KK; ky++) {
            const float* row = &tile[(y + ky)*TSTRIDE + x4];
            #pragma unroll
            for (int kx = 0; kx < KK; kx++) {
                float w = wgt[ky*KK + kx];
                a0 += row[kx+0] * w;
                a1 += row[kx+1] * w;
                a2 += row[kx+2] * w;
                a3 += row[kx+3] * w;
            }
        }
        op[idx] = make_float4(a0, a1, a2, a3);
    }
}

// ---------------------------------------------------------------------------
// 4) Pointwise: out[b,o,hw] = sum_c pw[o,c] * dwout[b,c,hw]
//    Per-b GEMM [256 x 256] @ [256 x 4096]. 64x64 tile, 16x16 threads, 4x4.
// ---------------------------------------------------------------------------
__global__ void pwconv_kernel(const float* __restrict__ pw,
                              float* __restrict__ out) {
    int b   = blockIdx.z;
    int o0  = blockIdx.y * 64;
    int hw0 = blockIdx.x * 64;
    const float* Bp = g_dwout + (size_t)b * CC * HW;

    __shared__ float As[64][17];    // [o][k]   (pad avoids conflicts)
    __shared__ float Bs[16][68];    // [k][hw]  (pad 4 keeps float4-friendly)

    int tid = threadIdx.y * 16 + threadIdx.x;
    float acc[4][4];
    #pragma unroll
    for (int u = 0; u < 4; u++)
        #pragma unroll
        for (int v = 0; v < 4; v++) acc[u][v] = 0.f;

    for (int kk = 0; kk < CC; kk += 16) {
        // load A tile: 64x16 = 1024 elems
        #pragma unroll
        for (int r = 0; r < 4; r++) {
            int idx = tid + r*256;
            int i = idx >> 4, j = idx & 15;
            As[i][j] = pw[(size_t)(o0 + i) * CC + kk + j];
        }
        // load B tile: 16 rows x 64 cols with float4 (256 vec loads, 1/thread)
        {
            int j = tid >> 4, i4 = (tid & 15) * 4;   // row 0..15, col
            float4 v = *(const float4*)&Bp[(size_t)(kk + j) * HW + hw0 + i4];
            Bs[j][i4+0] = v.x; Bs[j][i4+1] = v.y; Bs[j][i4+2] = v.z; Bs[j][i4+3] = v.w;
        }
        __syncthreads();
        #pragma unroll
        for (int j = 0; j < 16; j++) {
            float ar[4], br[4];
            #pragma unroll
            for (int u = 0; u < 4; u++) ar[u] = As[threadIdx.y*4 + u][j];
            #pragma unroll
            for (int v = 0; v < 4; v++) br[v] = Bs[j][threadIdx.x*4 + v];
            #pragma unroll
            for (int u = 0; u < 4; u++)
                #pragma unroll
                for (int v = 0; v < 4; v++)
                    acc[u][v] += ar[u] * br[v];
        }
        __syncthreads();
    }

    #pragma unroll
    for (int u = 0; u < 4; u++) {
        int o = o0 + threadIdx.y*4 + u;
        float* orow = out + ((size_t)b * CC + o) * HW + hw0 + threadIdx.x*4;
        *(float4*)orow = make_float4(acc[u][0], acc[u][1], acc[u][2], acc[u][3]);
    }
}

// ---------------------------------------------------------------------------
extern "C" void kernel_launch(void* const* d_in, const int* in_sizes, int n_in,
                              void* d_out, int out_size) {
    const float* x  = (const float*)d_in[0];
    const float* dw = (const float*)d_in[1];
    const float* pw = (const float*)d_in[2];
    const float* w1 = (const float*)d_in[3];
    const float* b1 = (const float*)d_in[4];
    const float* w2 = (const float*)d_in[5];
    const float* b2 = (const float*)d_in[6];
    float* out = (float*)d_out;

    pool_kernel<<<BB*CC, 256>>>(x);
    mlp1_kernel<<<BB, 64>>>(w1, b1);
    mlp2_kernel<<<BB*CC, 64>>>(dw, w2, b2);
    dwconv_kernel<<<BB*CC, 256>>>(x);
    dim3 g(HW/64, CC/64, BB);
    dim3 t(16, 16);
    pwconv_kernel<<<g, t>>>(pw, out);
}

// round 4
// speedup vs baseline: 1.5886x; 1.5886x over previous
#include <cuda_runtime.h>
#include <cuda_bf16.h>
#include <math.h>
#include <stdint.h>

// Problem constants
#define BB   16
#define CC   256
#define HH   64
#define WW   64
#define KK   7
#define HID  64          // C/4
#define HW   (HH*WW)     // 4096
#define KTAP (KK*KK)     // 49

// Scratch (device globals: sanctioned workaround for no-alloc rule)
__device__ float g_pooled[BB*CC];
__device__ float g_h[BB*HID];
__device__ float g_fused[BB*CC*KTAP];
__device__ __nv_bfloat16 g_pw_hi[CC*CC];
__device__ __nv_bfloat16 g_pw_lo[CC*CC];
__device__ __nv_bfloat16 g_dw_hi[(size_t)BB*CC*HW];   // 32 MiB
__device__ __nv_bfloat16 g_dw_lo[(size_t)BB*CC*HW];   // 32 MiB

static __device__ __forceinline__ uint32_t smem_u32(const void* p) {
    uint32_t a;
    asm("{ .reg .u64 t; cvta.to.shared.u64 t, %1; cvt.u32.u64 %0, t; }"
        : "=r"(a) : "l"(p));
    return a;
}
static __device__ __forceinline__ void ldsm_x4(uint32_t& r0, uint32_t& r1,
                                               uint32_t& r2, uint32_t& r3,
                                               uint32_t addr) {
    asm volatile("ldmatrix.sync.aligned.m8n8.x4.shared.b16 {%0,%1,%2,%3}, [%4];"
                 : "=r"(r0), "=r"(r1), "=r"(r2), "=r"(r3) : "r"(addr));
}
static __device__ __forceinline__ void ldsm_x4_t(uint32_t& r0, uint32_t& r1,
                                                 uint32_t& r2, uint32_t& r3,
                                                 uint32_t addr) {
    asm volatile("ldmatrix.sync.aligned.m8n8.x4.trans.shared.b16 {%0,%1,%2,%3}, [%4];"
                 : "=r"(r0), "=r"(r1), "=r"(r2), "=r"(r3) : "r"(addr));
}
static __device__ __forceinline__ void mma_bf16(float* c, const uint32_t* a,
                                                uint32_t b0, uint32_t b1) {
    asm volatile(
        "mma.sync.aligned.m16n8k16.row.col.f32.bf16.bf16.f32 "
        "{%0,%1,%2,%3}, {%4,%5,%6,%7}, {%8,%9}, {%0,%1,%2,%3};"
        : "+f"(c[0]), "+f"(c[1]), "+f"(c[2]), "+f"(c[3])
        : "r"(a[0]), "r"(a[1]), "r"(a[2]), "r"(a[3]), "r"(b0), "r"(b1));
}

// ---------------------------------------------------------------------------
// 1) Global average pool
// ---------------------------------------------------------------------------
__global__ void pool_kernel(const float* __restrict__ x) {
    int bc = blockIdx.x;
    const float4* p = (const float4*)(x + (size_t)bc * HW);
    float s = 0.f;
    #pragma unroll
    for (int i = 0; i < HW/4/256; i++) {
        float4 v = p[threadIdx.x + i*256];
        s += (v.x + v.y) + (v.z + v.w);
    }
    for (int o = 16; o > 0; o >>= 1) s += __shfl_down_sync(0xffffffffu, s, o);
    __shared__ float partial[8];
    if ((threadIdx.x & 31) == 0) partial[threadIdx.x >> 5] = s;
    __syncthreads();
    if (threadIdx.x == 0) {
        float t = 0.f;
        #pragma unroll
        for (int w = 0; w < 8; w++) t += partial[w];
        g_pooled[bc] = t * (1.0f / HW);
    }
}

// ---------------------------------------------------------------------------
// 2a) h = gelu(pooled @ w1.T + b1)
// ---------------------------------------------------------------------------
__global__ void mlp1_kernel(const float* __restrict__ w1,
                            const float* __restrict__ b1) {
    int b = blockIdx.x;
    __shared__ float sp[CC];
    for (int i = threadIdx.x; i < CC; i += 64) sp[i] = g_pooled[b*CC + i];
    __syncthreads();
    int j = threadIdx.x;
    const float* wr = w1 + (size_t)j * CC;
    float acc = b1[j];
    #pragma unroll 8
    for (int c = 0; c < CC; c++) acc += sp[c] * wr[c];
    g_h[b*HID + j] = 0.5f * acc * (1.0f + erff(acc * 0.70710678118654752f));
}

// ---------------------------------------------------------------------------
// 2b) fused weights
// ---------------------------------------------------------------------------
__global__ void mlp2_kernel(const float* __restrict__ dw_weight,
                            const float* __restrict__ w2,
                            const float* __restrict__ b2) {
    int bc = blockIdx.x;
    int b = bc / CC, c = bc % CC;
    __shared__ float sh[HID];
    if (threadIdx.x < HID) sh[threadIdx.x] = g_h[b*HID + threadIdx.x];
    __syncthreads();
    int t = threadIdx.x;
    if (t < KTAP) {
        int m = c * KTAP + t;
        const float* wr = w2 + (size_t)m * HID;
        float acc = b2[m];
        #pragma unroll
        for (int j = 0; j < HID; j++) acc += sh[j] * wr[j];
        g_fused[(size_t)bc * KTAP + t] = dw_weight[m] + acc;
    }
}

// ---------------------------------------------------------------------------
// 2c) split pw into bf16 hi/lo
// ---------------------------------------------------------------------------
__global__ void pwsplit_kernel(const float* __restrict__ pw) {
    int i = blockIdx.x * 256 + threadIdx.x;
    float v = pw[i];
    __nv_bfloat16 h = __float2bfloat16(v);
    g_pw_hi[i] = h;
    g_pw_lo[i] = __float2bfloat16(v - __bfloat162float(h));
}

// ---------------------------------------------------------------------------
// 3) Depthwise 7x7 conv -> bf16 hi/lo split output
// ---------------------------------------------------------------------------
#define TS 70
#define TSTRIDE 72
__global__ void dwconv_kernel(const float* __restrict__ x) {
    int bc = blockIdx.x;
    __shared__ float tile[TS * TSTRIDE];
    __shared__ float wgt[KTAP];
    if (threadIdx.x < KTAP) wgt[threadIdx.x] = g_fused[(size_t)bc * KTAP + threadIdx.x];

    const float* xp = x + (size_t)bc * HW;
    {
        const float4* xv = (const float4*)xp;
        #pragma unroll
        for (int r = 0; r < 4; r++) {
            int idx = threadIdx.x + r*256;
            int gy = idx >> 4, gx4 = idx & 15;
            float4 v = xv[gy*16 + gx4];
            float* d = &tile[(gy+3)*TSTRIDE + 3 + gx4*4];
            d[0] = v.x; d[1] = v.y; d[2] = v.z; d[3] = v.w;
        }
    }
    for (int i = threadIdx.x; i < TS*3; i += 256) {
        int ty = i / TS, tx = i % TS;
        tile[ty*TSTRIDE + tx] = 0.f;
        tile[(ty+67)*TSTRIDE + tx] = 0.f;
    }
    for (int i = threadIdx.x; i < 64*3; i += 256) {
        int ty = i / 3 + 3, tx = i % 3;
        tile[ty*TSTRIDE + tx] = 0.f;
        tile[ty*TSTRIDE + 67 + tx] = 0.f;
    }
    __syncthreads();

    uint2* oph = (uint2*)(g_dw_hi + (size_t)bc * HW);
    uint2* opl = (uint2*)(g_dw_lo + (size_t)bc * HW);
    #pragma unroll
    for (int i = 0; i < 4; i++) {
        int idx = threadIdx.x + i*256;
        int y = idx >> 4, x4 = (idx & 15) * 4;
        float a[4] = {0.f, 0.f, 0.f, 0.f};
        #pragma unroll
        for (int ky = 0; ky < KK; ky++) {
            const float* row = &tile[(y + ky)*TSTRIDE + x4];
            #pragma unroll
            for (int kx = 0; kx < KK; kx++) {
                float w = wgt[ky*KK + kx];
                a[0] += row[kx+0] * w;
                a[1] += row[kx+1] * w;
                a[2] += row[kx+2] * w;
                a[3] += row[kx+3] * w;
            }
        }
        uint32_t hbits[4], lbits[4];
        #pragma unroll
        for (int q = 0; q < 4; q++) {
            __nv_bfloat16 h = __float2bfloat16(a[q]);
            __nv_bfloat16 l = __float2bfloat16(a[q] - __bfloat162float(h));
            hbits[q] = (uint32_t)__bfloat16_as_ushort(h);
            lbits[q] = (uint32_t)__bfloat16_as_ushort(l);
        }
        oph[idx] = make_uint2(hbits[0] | (hbits[1] << 16), hbits[2] | (hbits[3] << 16));
        opl[idx] = make_uint2(lbits[0] | (lbits[1] << 16), lbits[2] | (lbits[3] << 16));
    }
}

// ---------------------------------------------------------------------------
// 4) Pointwise GEMM via mma.sync bf16 3-pass split (hi*hi + hi*lo + lo*hi).
//    Per b: out[o,p] = sum_c pw[o,c]*dwout[c,p].  Block tile 128(M=o)x64(N=p),
//    K-chunk 32. 8 warps, warp tile 32x32.
// ---------------------------------------------------------------------------
#define Bb_M 128
#define Bb_N 64
#define Bb_K 32
#define A_PAD 40      // bf16 elems per A row (32 + 8) = 80 B, conflict-free
#define B_PAD 72      // bf16 elems per B row (64 + 8) = 144 B, conflict-free

__global__ void __launch_bounds__(256) pw_mma_kernel(float* __restrict__ out) {
    __shared__ __nv_bfloat16 sAh[Bb_M * A_PAD];
    __shared__ __nv_bfloat16 sAl[Bb_M * A_PAD];
    __shared__ __nv_bfloat16 sBh[Bb_K * B_PAD];
    __shared__ __nv_bfloat16 sBl[Bb_K * B_PAD];

    const int tid  = threadIdx.x;
    const int lane = tid & 31;
    const int wid  = tid >> 5;
    const int wm   = wid & 3;           // warp M block (0..3) -> rows wm*32
    const int wn   = wid >> 2;          // warp N block (0..1) -> cols wn*32
    const int p0   = blockIdx.x * Bb_N;
    const int o0   = blockIdx.y * Bb_M;
    const int b    = blockIdx.z;

    const __nv_bfloat16* dwh = g_dw_hi + (size_t)b * CC * HW;
    const __nv_bfloat16* dwl = g_dw_lo + (size_t)b * CC * HW;

    const uint32_t aHb = smem_u32(sAh), aLb = smem_u32(sAl);
    const uint32_t bHb = smem_u32(sBh), bLb = smem_u32(sBl);

    float acc[2][4][4];
    #pragma unroll
    for (int mi = 0; mi < 2; mi++)
        #pragma unroll
        for (int ni = 0; ni < 4; ni++)
            #pragma unroll
            for (int q = 0; q < 4; q++) acc[mi][ni][q] = 0.f;

    // ldmatrix lane addressing pieces
    const int lmat = lane >> 3, lrow = lane & 7;
    // A: m = base + lrow + (lmat&1)*8 ; k = kk + (lmat>>1)*8
    const int a_m_off = lrow + (lmat & 1) * 8;
    const int a_k_off = (lmat >> 1) * 8;
    // B (trans): k = kk + lrow + (lmat&1)*8 ; n = nbase + (lmat>>1)*8
    const int b_k_off = lrow + (lmat & 1) * 8;
    const int b_n_off = (lmat >> 1) * 8;

    for (int kc = 0; kc < CC; kc += Bb_K) {
        // --- A tiles: 128 rows x 32 k, 16B chunks; 512 chunks per split ---
        #pragma unroll
        for (int s = 0; s < 2; s++) {
            int idx = tid + s*256;          // 0..511
            int m = idx >> 2, ch = idx & 3; // row, 16B chunk
            uint4 vh = *(const uint4*)(g_pw_hi + (size_t)(o0 + m) * CC + kc + ch*8);
            uint4 vl = *(const uint4*)(g_pw_lo + (size_t)(o0 + m) * CC + kc + ch*8);
            *(uint4*)(sAh + m*A_PAD + ch*8) = vh;
            *(uint4*)(sAl + m*A_PAD + ch*8) = vl;
        }
        // --- B tiles: 32 k rows x 64 n, 8 chunks/row; 256 chunks per split ---
        {
            int m = tid >> 3, ch = tid & 7;
            uint4 vh = *(const uint4*)(dwh + (size_t)(kc + m) * HW + p0 + ch*8);
            uint4 vl = *(const uint4*)(dwl + (size_t)(kc + m) * HW + p0 + ch*8);
            *(uint4*)(sBh + m*B_PAD + ch*8) = vh;
            *(uint4*)(sBl + m*B_PAD + ch*8) = vl;
        }
        __syncthreads();

        #pragma unroll
        for (int kk = 0; kk < Bb_K; kk += 16) {
            uint32_t ah[2][4], al[2][4];
            #pragma unroll
            for (int mi = 0; mi < 2; mi++) {
                int m = wm*32 + mi*16 + a_m_off;
                int k = kk + a_k_off;
                ldsm_x4(ah[mi][0], ah[mi][1], ah[mi][2], ah[mi][3],
                        aHb + (m*A_PAD + k)*2);
                ldsm_x4(al[mi][0], al[mi][1], al[mi][2], al[mi][3],
                        aLb + (m*A_PAD + k)*2);
            }
            uint32_t bh[2][4], bl[2][4];
            #pragma unroll
            for (int nb = 0; nb < 2; nb++) {
                int k = kk + b_k_off;
                int n = wn*32 + nb*16 + b_n_off;
                ldsm_x4_t(bh[nb][0], bh[nb][1], bh[nb][2], bh[nb][3],
                          bHb + (k*B_PAD + n)*2);
                ldsm_x4_t(bl[nb][0], bl[nb][1], bl[nb][2], bl[nb][3],
                          bLb + (k*B_PAD + n)*2);
            }
            #pragma unroll
            for (int mi = 0; mi < 2; mi++) {
                #pragma unroll
                for (int ni = 0; ni < 4; ni++) {
                    int nb = ni >> 1, hi = (ni & 1) * 2;
                    uint32_t b0h = bh[nb][hi], b1h = bh[nb][hi+1];
                    uint32_t b0l = bl[nb][hi], b1l = bl[nb][hi+1];
                    mma_bf16(acc[mi][ni], ah[mi], b0h, b1h);
                    mma_bf16(acc[mi][ni], ah[mi], b0l, b1l);
                    mma_bf16(acc[mi][ni], al[mi], b0h, b1h);
                }
            }
        }
        __syncthreads();
    }

    // Epilogue: c0,c1 -> (row, col+0/1), c2,c3 -> (row+8, col+0/1)
    const int crow = lane >> 2, ccol = (lane & 3) * 2;
    #pragma unroll
    for (int mi = 0; mi < 2; mi++) {
        #pragma unroll
        for (int ni = 0; ni < 4; ni++) {
            int o = o0 + wm*32 + mi*16 + crow;
            int p = p0 + wn*32 + ni*8 + ccol;
            float* d0 = out + ((size_t)(b*CC + o)) * HW + p;
            float* d1 = out + ((size_t)(b*CC + o + 8)) * HW + p;
            *(float2*)d0 = make_float2(acc[mi][ni][0], acc[mi][ni][1]);
            *(float2*)d1 = make_float2(acc[mi][ni][2], acc[mi][ni][3]);
        }
    }
}

// ---------------------------------------------------------------------------
extern "C" void kernel_launch(void* const* d_in, const int* in_sizes, int n_in,
                              void* d_out, int out_size) {
    const float* x  = (const float*)d_in[0];
    const float* dw = (const float*)d_in[1];
    const float* pw = (const float*)d_in[2];
    const float* w1 = (const float*)d_in[3];
    const float* b1 = (const float*)d_in[4];
    const float* w2 = (const float*)d_in[5];
    const float* b2 = (const float*)d_in[6];
    float* out = (float*)d_out;

    pool_kernel<<<BB*CC, 256>>>(x);
    mlp1_kernel<<<BB, 64>>>(w1, b1);
    pwsplit_kernel<<<CC*CC/256, 256>>>(pw);
    mlp2_kernel<<<BB*CC, 64>>>(dw, w2, b2);
    dwconv_kernel<<<BB*CC, 256>>>(x);
    dim3 g(HW/Bb_N, CC/Bb_M, BB);
    pw_mma_kernel<<<g, 256>>>(out);
}